// round 8
// baseline (speedup 1.0000x reference)
#include <cuda_runtime.h>
#include <cuda_bf16.h>
#include <math.h>

// Problem constants
#define BATCH   128
#define C_IN    64
#define C_OUT   64
#define LSEQ    512
#define POSTC   384
#define HID     1024
#define OUT_DIM 128
#define LOGSIG  2080          // 64 + 64*63/2
#define IN_DIM  2464          // LOGSIG + POSTC
#define XCH     448           // C_IN + POSTC

// Scratch (device globals: allocation-free per harness rules)
__device__ float g_path[BATCH * LSEQ * C_OUT];   // (B, L, C) c-contiguous
__device__ float g_feat[BATCH * IN_DIM];
__device__ float g_h1[BATCH * HID];
__device__ float g_h2[BATCH * HID];
__device__ float g_part[4 * BATCH * HID];        // split-K partials (max S*M*N)
__device__ float g_spart[2 * BATCH * 64 * 64];   // sig partial S per half

// fast tanh via MUFU.EX2: rel err ~2^-20, well under the 1e-3 gate
__device__ __forceinline__ float tanh_fast(float x)
{
    float ax = fabsf(x);
    float t  = __expf(-2.f * ax);          // e^{-2|x|}
    float r  = (1.f - t) * __frcp_rn(1.f + t);
    return copysignf(r, x);
}

// ---------------------------------------------------------------------------
// Kernel 1: conv1d(k=3, pad=1) + bias + tanh -> path (B, L, 64)
// grid (8, 128): blockIdx.x = t-tile (64 wide), blockIdx.y = batch
// 256 threads as 16(tx: t) x 16(ty: c); each thread computes 4c x 4t.
// Weights staged in smem in FOUR ci-phases (16 ci each): smem ~28.8KB
// -> 2 blocks/SM (16 warps) for latency hiding.
// ---------------------------------------------------------------------------
__global__ __launch_bounds__(256) void conv_tanh_kernel(
    const float* __restrict__ x, const float* __restrict__ w,
    const float* __restrict__ bias)
{
    __shared__ float ws[48 * 64];      // [ci_local*3+k][c]  (one phase: 16 ci)
    __shared__ float xs[64 * 66];      // [ci][tt], tt = t - t0 + 1 (halo)

    const int b  = blockIdx.y;
    const int t0 = blockIdx.x * 64;
    const int tid = threadIdx.x;
    const int tx = tid & 15;           // t group
    const int ty = tid >> 4;           // c group

    // x tile interior: LDG.128 (t0..t0+63 always in-bounds), halo scalar.
    for (int e = tid * 4; e < 64 * 64; e += 256 * 4) {
        int ci = e >> 6, q = e & 63;   // t = t0 + q
        float4 g = *(const float4*)&x[(b * XCH + ci) * LSEQ + t0 + q];
        float* d = &xs[ci * 66 + q + 1];
        d[0] = g.x; d[1] = g.y; d[2] = g.z; d[3] = g.w;
    }
    if (tid < 128) {                   // halo: tt=0 (t0-1) and tt=65 (t0+64)
        int ci = tid & 63;
        if (tid < 64) {
            int t = t0 - 1;
            xs[ci * 66 + 0] = (t >= 0) ? x[(b * XCH + ci) * LSEQ + t] : 0.f;
        } else {
            int t = t0 + 64;
            xs[ci * 66 + 65] = (t < LSEQ) ? x[(b * XCH + ci) * LSEQ + t] : 0.f;
        }
    }

    float acc[4][4] = {};

    #pragma unroll 1
    for (int ph = 0; ph < 4; ph++) {
        __syncthreads();
        // weights: ws[(cil*3+k)*64 + c] = w[(c*64+ci)*3+k].
        // For fixed c, (cil,k) spans 48 contiguous floats at (c*64+ph*16)*3.
        for (int e = tid; e < 64 * 12; e += 256) {
            int c = e & 63, rg = e >> 6;             // rg in [0,12): group of 4 r
            float4 g = *(const float4*)&w[(c * 64 + ph * 16) * 3 + rg * 4];
            ws[(rg * 4 + 0) * 64 + c] = g.x;
            ws[(rg * 4 + 1) * 64 + c] = g.y;
            ws[(rg * 4 + 2) * 64 + c] = g.z;
            ws[(rg * 4 + 3) * 64 + c] = g.w;
        }
        __syncthreads();

        #pragma unroll 4
        for (int cil = 0; cil < 16; cil++) {
            const int ci = ph * 16 + cil;
            float xv[6];
            #pragma unroll
            for (int m = 0; m < 6; m++) xv[m] = xs[ci * 66 + tx * 4 + m];
            #pragma unroll
            for (int k = 0; k < 3; k++) {
                float4 a4 = *(const float4*)&ws[(cil * 3 + k) * 64 + ty * 4];
                float av[4] = {a4.x, a4.y, a4.z, a4.w};
                #pragma unroll
                for (int i = 0; i < 4; i++)
                    #pragma unroll
                    for (int j = 0; j < 4; j++)
                        acc[i][j] += av[i] * xv[j + k];
            }
        }
    }

    // epilogue: tanh + bias, stage transposed in smem for coalesced writes
    __syncthreads();
    float* ss = xs;                    // reuse xs: need 64*65 = 4160 <= 4224
    float bv[4];
    #pragma unroll
    for (int i = 0; i < 4; i++) bv[i] = bias[ty * 4 + i];
    #pragma unroll
    for (int i = 0; i < 4; i++)
        #pragma unroll
        for (int j = 0; j < 4; j++)
            ss[(tx * 4 + j) * 65 + ty * 4 + i] = tanh_fast(acc[i][j] + bv[i]);
    __syncthreads();

    float* pout = g_path + (b * LSEQ + t0) * 64;
    for (int e = tid; e < 64 * 64; e += 256) {
        int t = e >> 6, c = e & 63;
        pout[e] = ss[t * 65 + c];      // e = t*64 + c  (coalesced)
    }
}

// ---------------------------------------------------------------------------
// Kernel 2a: partial depth-2 signature level-2 matrix.
// grid (2, 128): blockIdx.x = half h (t-steps [h*256, min((h+1)*256, 511))),
// blockIdx.y = batch. 256 threads as 16(tx: j) x 16(ty: i), 4x4 reg tiles.
// S_h[i][j] = sum_{t in half} (path[t]-path[0])_i * (path[t+1]-path[t])_j
// ---------------------------------------------------------------------------
__global__ __launch_bounds__(256) void sig_part_kernel(void)
{
    __shared__ float ps[65 * 64];      // [tt][ci]
    const int h = blockIdx.x, b = blockIdx.y, tid = threadIdx.x;
    const int tx = tid & 15, ty = tid >> 4;
    const float* pb = g_path + b * LSEQ * 64;

    float p0[4];
    #pragma unroll
    for (int i = 0; i < 4; i++) p0[i] = pb[ty * 4 + i];

    float acc[4][4] = {};

    const int tbeg = h * 256;
    const int tend = min((h + 1) * 256, LSEQ - 1);
    for (int t0 = tbeg; t0 < tend; t0 += 64) {
        const int steps = min(64, tend - t0);
        const int nrows = steps + 1;
        __syncthreads();
        for (int e = tid * 4; e < nrows * 64; e += 256 * 4) {
            float4 g = *(const float4*)&pb[t0 * 64 + e];
            *(float4*)&ps[e] = g;
        }
        __syncthreads();

        float4 cur = *(const float4*)&ps[tx * 4];
        #pragma unroll 4
        for (int t = 0; t < steps; t++) {
            float4 pf4 = *(const float4*)&ps[t * 64 + ty * 4];
            float4 nxt = *(const float4*)&ps[(t + 1) * 64 + tx * 4];
            float pf[4] = {pf4.x - p0[0], pf4.y - p0[1], pf4.z - p0[2], pf4.w - p0[3]};
            float df[4] = {nxt.x - cur.x, nxt.y - cur.y, nxt.z - cur.z, nxt.w - cur.w};
            #pragma unroll
            for (int i = 0; i < 4; i++)
                #pragma unroll
                for (int j = 0; j < 4; j++)
                    acc[i][j] += pf[i] * df[j];
            cur = nxt;
        }
    }

    float* sp = g_spart + (b * 2 + h) * 64 * 64;
    #pragma unroll
    for (int i = 0; i < 4; i++)
        #pragma unroll
        for (int j = 0; j < 4; j++)
            sp[(ty * 4 + i) * 64 + tx * 4 + j] = acc[i][j];
}

// ---------------------------------------------------------------------------
// Kernel 2b: combine partial S, Levy area + lvl1 + tail features.
// grid 128 (batch), 256 threads.
// ---------------------------------------------------------------------------
__global__ __launch_bounds__(256) void sig_combine_kernel(const float* __restrict__ x)
{
    __shared__ float red[256];
    const int b = blockIdx.x, tid = threadIdx.x;
    const float* pb = g_path + b * LSEQ * 64;
    const float* sp0 = g_spart + (b * 2 + 0) * 64 * 64;
    const float* sp1 = g_spart + (b * 2 + 1) * 64 * 64;
    float* fb = g_feat + b * IN_DIM;

    // tail: max-pool channel 64, static = channels 65.. at t=0
    {
        const float* xr = x + (b * XCH + C_IN) * LSEQ;
        float m = -3.402823466e+38f;
        #pragma unroll
        for (int t = tid; t < LSEQ; t += 256) m = fmaxf(m, xr[t]);
        red[tid] = m;
        __syncthreads();
        for (int s = 128; s > 0; s >>= 1) {
            if (tid < s) red[tid] = fmaxf(red[tid], red[tid + s]);
            __syncthreads();
        }
        if (tid == 0) fb[LOGSIG] = red[0];
        for (int c = tid; c < POSTC - 1; c += 256)
            fb[LOGSIG + 1 + c] = x[(b * XCH + C_IN + 1 + c) * LSEQ + 0];
    }

    if (tid < 64) fb[tid] = pb[(LSEQ - 1) * 64 + tid] - pb[tid];  // level 1

    for (int u = tid; u < 2016; u += 256) {
        int i = 0, rem = u;
        while (rem >= 63 - i) { rem -= 63 - i; i++; }
        int j = i + 1 + rem;
        float sij = sp0[i * 64 + j] + sp1[i * 64 + j];
        float sji = sp0[j * 64 + i] + sp1[j * 64 + i];
        fb[64 + u] = 0.5f * (sij - sji);
    }
}

// ---------------------------------------------------------------------------
// Split-K FC GEMM, double-buffered smem + register prefetch.
// part[z][m][n] = sum_{k in chunk z} A[m][k] * W[n][k]
// A: [M][K] row-major, W: [N][K] row-major. BK = 32, K % 32 == 0.
// 256 threads as 16(tx: n) x 16(ty: m); thread tile TM x TN.
// One __syncthreads per K-chunk; next chunk's LDG overlapped with compute.
// ---------------------------------------------------------------------------
template<int BM, int BN, int TM, int TN, int S>
__global__ __launch_bounds__(256) void fc_part_kernel(
    const float* __restrict__ A, const float* __restrict__ W,
    float* __restrict__ part, int M, int N, int K)
{
    constexpr int BK = 32;
    constexpr int NA = (BM * BK) / 1024;   // float4 loads per thread (A)
    constexpr int NB = (BN * BK) / 1024;   // float4 loads per thread (B)
    __shared__ float aT[2][BK][BM + 4];
    __shared__ float bT[2][BK][BN + 4];

    const int m0 = blockIdx.y * BM, n0 = blockIdx.x * BN;
    const int z = blockIdx.z;
    const int chunks = K / BK;
    const int kb = (z * chunks / S) * BK;
    const int ke = ((z + 1) * chunks / S) * BK;
    const int tid = threadIdx.x, tx = tid & 15, ty = tid >> 4;

    float4 ra[NA], rb[NB];
    float acc[TM][TN] = {};

    auto fetch = [&](int k0) {
        #pragma unroll
        for (int i = 0; i < NA; i++) {
            int e = tid * 4 + i * 1024;
            ra[i] = *(const float4*)&A[(m0 + (e >> 5)) * K + k0 + (e & 31)];
        }
        #pragma unroll
        for (int i = 0; i < NB; i++) {
            int e = tid * 4 + i * 1024;
            rb[i] = *(const float4*)&W[(n0 + (e >> 5)) * K + k0 + (e & 31)];
        }
    };
    auto stage = [&](int buf) {
        #pragma unroll
        for (int i = 0; i < NA; i++) {
            int e = tid * 4 + i * 1024, r = e >> 5, c = e & 31;
            aT[buf][c + 0][r] = ra[i].x; aT[buf][c + 1][r] = ra[i].y;
            aT[buf][c + 2][r] = ra[i].z; aT[buf][c + 3][r] = ra[i].w;
        }
        #pragma unroll
        for (int i = 0; i < NB; i++) {
            int e = tid * 4 + i * 1024, r = e >> 5, c = e & 31;
            bT[buf][c + 0][r] = rb[i].x; bT[buf][c + 1][r] = rb[i].y;
            bT[buf][c + 2][r] = rb[i].z; bT[buf][c + 3][r] = rb[i].w;
        }
    };
    auto compute = [&](int buf) {
        #pragma unroll
        for (int kk = 0; kk < BK; kk++) {
            float af[TM], bf[TN];
            if (TM == 4) {
                float4 a4 = *(const float4*)&aT[buf][kk][ty * 4];
                af[0] = a4.x; af[1] = a4.y; af[2] = a4.z; af[3] = a4.w;
            } else {
                #pragma unroll
                for (int i = 0; i < TM; i++) af[i] = aT[buf][kk][ty * TM + i];
            }
            if (TN == 4) {
                float4 b4 = *(const float4*)&bT[buf][kk][tx * 4];
                bf[0] = b4.x; bf[1] = b4.y; bf[2] = b4.z; bf[3] = b4.w;
            } else {
                #pragma unroll
                for (int j = 0; j < TN; j++) bf[j] = bT[buf][kk][tx * TN + j];
            }
            #pragma unroll
            for (int i = 0; i < TM; i++)
                #pragma unroll
                for (int j = 0; j < TN; j++)
                    acc[i][j] += af[i] * bf[j];
        }
    };

    fetch(kb);
    stage(0);
    __syncthreads();
    int buf = 0;
    for (int k0 = kb + BK; k0 < ke; k0 += BK) {
        fetch(k0);          // overlaps with compute below
        compute(buf);
        stage(buf ^ 1);     // other buffer: no reader this iteration
        __syncthreads();    // staging visible before next compute
        buf ^= 1;
    }
    compute(buf);

    float* pz = part + (size_t)z * M * N;
    #pragma unroll
    for (int i = 0; i < TM; i++) {
        int m = m0 + ty * TM + i;
        #pragma unroll
        for (int j = 0; j < TN; j++) {
            int n = n0 + tx * TN + j;
            pz[m * N + n] = acc[i][j];
        }
    }
}

// reduce partials + bias (+ relu)
template<int S, bool RELU>
__global__ __launch_bounds__(256) void fc_reduce_kernel(
    const float* __restrict__ part, const float* __restrict__ bias,
    float* __restrict__ out, int M, int N)
{
    int idx = blockIdx.x * 256 + threadIdx.x;
    if (idx >= M * N) return;
    int n = idx % N;
    float v = bias[n];
    #pragma unroll
    for (int z = 0; z < S; z++) v += part[(size_t)z * M * N + idx];
    if (RELU) v = fmaxf(v, 0.f);
    out[idx] = v;
}

// ---------------------------------------------------------------------------
extern "C" void kernel_launch(void* const* d_in, const int* in_sizes, int n_in,
                              void* d_out, int out_size)
{
    const float* x      = (const float*)d_in[0];
    const float* conv_w = (const float*)d_in[1];
    const float* conv_b = (const float*)d_in[2];
    const float* fc1_w  = (const float*)d_in[3];
    const float* fc1_b  = (const float*)d_in[4];
    const float* fc2_w  = (const float*)d_in[5];
    const float* fc2_b  = (const float*)d_in[6];
    const float* fc3_w  = (const float*)d_in[7];
    const float* fc3_b  = (const float*)d_in[8];
    float* out = (float*)d_out;

    float *p_feat, *p_h1, *p_h2, *p_part;
    cudaGetSymbolAddress((void**)&p_feat, g_feat);
    cudaGetSymbolAddress((void**)&p_h1, g_h1);
    cudaGetSymbolAddress((void**)&p_h2, g_h2);
    cudaGetSymbolAddress((void**)&p_part, g_part);

    conv_tanh_kernel<<<dim3(LSEQ / 64, BATCH), 256>>>(x, conv_w, conv_b);
    sig_part_kernel<<<dim3(2, BATCH), 256>>>();
    sig_combine_kernel<<<BATCH, 256>>>(x);

    // fc1: 128 x 1024 x 2464, tiles 64x64, split-K 4 -> 128 blocks
    fc_part_kernel<64, 64, 4, 4, 4><<<dim3(HID / 64, BATCH / 64, 4), 256>>>(
        p_feat, fc1_w, p_part, BATCH, HID, IN_DIM);
    fc_reduce_kernel<4, true><<<(BATCH * HID + 255) / 256, 256>>>(
        p_part, fc1_b, p_h1, BATCH, HID);

    // fc2: 128 x 1024 x 1024, tiles 64x64, split-K 4 -> 128 blocks
    fc_part_kernel<64, 64, 4, 4, 4><<<dim3(HID / 64, BATCH / 64, 4), 256>>>(
        p_h1, fc2_w, p_part, BATCH, HID, HID);
    fc_reduce_kernel<4, true><<<(BATCH * HID + 255) / 256, 256>>>(
        p_part, fc2_b, p_h2, BATCH, HID);

    // fc3: 128 x 128 x 1024, tiles 32x32, split-K 8 -> 128 blocks (no relu)
    fc_part_kernel<32, 32, 2, 2, 8><<<dim3(OUT_DIM / 32, BATCH / 32, 8), 256>>>(
        p_h2, fc3_w, p_part, BATCH, OUT_DIM, HID);
    fc_reduce_kernel<8, false><<<(BATCH * OUT_DIM + 255) / 256, 256>>>(
        p_part, fc3_b, out, BATCH, OUT_DIM);
}

// round 14
// speedup vs baseline: 1.0357x; 1.0357x over previous
#include <cuda_runtime.h>
#include <cuda_bf16.h>
#include <math.h>

// Problem constants
#define BATCH   128
#define C_IN    64
#define C_OUT   64
#define LSEQ    512
#define POSTC   384
#define HID     1024
#define OUT_DIM 128
#define LOGSIG  2080          // 64 + 64*63/2
#define IN_DIM  2464          // LOGSIG + POSTC
#define XCH     448           // C_IN + POSTC

// Scratch (device globals: allocation-free per harness rules)
__device__ float g_path[BATCH * LSEQ * C_OUT];   // (B, L, C) c-contiguous
__device__ float g_feat[BATCH * IN_DIM];
__device__ float g_h1[BATCH * HID];
__device__ float g_h2[BATCH * HID];
__device__ float g_part[8 * BATCH * HID];        // split-K partials (max S*M*N)
__device__ float g_spart[2 * BATCH * 64 * 64];   // sig partial S per half

// fast tanh via MUFU.EX2: rel err ~2^-20, well under the 1e-3 gate
__device__ __forceinline__ float tanh_fast(float x)
{
    float ax = fabsf(x);
    float t  = __expf(-2.f * ax);          // e^{-2|x|}
    float r  = (1.f - t) * __frcp_rn(1.f + t);
    return copysignf(r, x);
}

// ---------------------------------------------------------------------------
// Kernel 1: conv1d(k=3, pad=1) + bias + tanh -> path (B, L, 64)
// grid (8, 128): blockIdx.x = t-tile (64 wide), blockIdx.y = batch
// 256 threads as 16(tx: t) x 16(ty: c); each thread computes 4c x 4t.
// __launch_bounds__(256,2): explicit 2-CTA/SM residency (smem 28.8KB each).
// ---------------------------------------------------------------------------
__global__ __launch_bounds__(256, 2) void conv_tanh_kernel(
    const float* __restrict__ x, const float* __restrict__ w,
    const float* __restrict__ bias)
{
    __shared__ float ws[48 * 64];      // [ci_local*3+k][c]  (one phase: 16 ci)
    __shared__ float xs[64 * 66];      // [ci][tt], tt = t - t0 + 1 (halo)

    const int b  = blockIdx.y;
    const int t0 = blockIdx.x * 64;
    const int tid = threadIdx.x;
    const int tx = tid & 15;           // t group
    const int ty = tid >> 4;           // c group

    // x tile interior: LDG.128 (t0..t0+63 always in-bounds), halo scalar.
    for (int e = tid * 4; e < 64 * 64; e += 256 * 4) {
        int ci = e >> 6, q = e & 63;   // t = t0 + q
        float4 g = *(const float4*)&x[(b * XCH + ci) * LSEQ + t0 + q];
        float* d = &xs[ci * 66 + q + 1];
        d[0] = g.x; d[1] = g.y; d[2] = g.z; d[3] = g.w;
    }
    if (tid < 128) {                   // halo: tt=0 (t0-1) and tt=65 (t0+64)
        int ci = tid & 63;
        if (tid < 64) {
            int t = t0 - 1;
            xs[ci * 66 + 0] = (t >= 0) ? x[(b * XCH + ci) * LSEQ + t] : 0.f;
        } else {
            int t = t0 + 64;
            xs[ci * 66 + 65] = (t < LSEQ) ? x[(b * XCH + ci) * LSEQ + t] : 0.f;
        }
    }

    float acc[4][4] = {};

    #pragma unroll 1
    for (int ph = 0; ph < 4; ph++) {
        __syncthreads();
        // weights: ws[(cil*3+k)*64 + c] = w[(c*64+ci)*3+k].
        for (int e = tid; e < 64 * 12; e += 256) {
            int c = e & 63, rg = e >> 6;             // rg in [0,12): group of 4 r
            float4 g = *(const float4*)&w[(c * 64 + ph * 16) * 3 + rg * 4];
            ws[(rg * 4 + 0) * 64 + c] = g.x;
            ws[(rg * 4 + 1) * 64 + c] = g.y;
            ws[(rg * 4 + 2) * 64 + c] = g.z;
            ws[(rg * 4 + 3) * 64 + c] = g.w;
        }
        __syncthreads();

        #pragma unroll 4
        for (int cil = 0; cil < 16; cil++) {
            const int ci = ph * 16 + cil;
            float xv[6];
            #pragma unroll
            for (int m = 0; m < 6; m++) xv[m] = xs[ci * 66 + tx * 4 + m];
            #pragma unroll
            for (int k = 0; k < 3; k++) {
                float4 a4 = *(const float4*)&ws[(cil * 3 + k) * 64 + ty * 4];
                float av[4] = {a4.x, a4.y, a4.z, a4.w};
                #pragma unroll
                for (int i = 0; i < 4; i++)
                    #pragma unroll
                    for (int j = 0; j < 4; j++)
                        acc[i][j] += av[i] * xv[j + k];
            }
        }
    }

    // epilogue: tanh + bias, stage transposed in smem for coalesced writes
    __syncthreads();
    float* ss = xs;                    // reuse xs: need 64*65 = 4160 <= 4224
    float bv[4];
    #pragma unroll
    for (int i = 0; i < 4; i++) bv[i] = bias[ty * 4 + i];
    #pragma unroll
    for (int i = 0; i < 4; i++)
        #pragma unroll
        for (int j = 0; j < 4; j++)
            ss[(tx * 4 + j) * 65 + ty * 4 + i] = tanh_fast(acc[i][j] + bv[i]);
    __syncthreads();

    float* pout = g_path + (b * LSEQ + t0) * 64;
    for (int e = tid; e < 64 * 64; e += 256) {
        int t = e >> 6, c = e & 63;
        pout[e] = ss[t * 65 + c];      // e = t*64 + c  (coalesced)
    }
}

// ---------------------------------------------------------------------------
// Kernel 2a: partial depth-2 signature level-2 matrix.
// grid (2, 128): blockIdx.x = half h (t-steps [h*256, min((h+1)*256, 511))),
// blockIdx.y = batch. 256 threads as 16(tx: j) x 16(ty: i), 4x4 reg tiles.
// S_h[i][j] = sum_{t in half} (path[t]-path[0])_i * (path[t+1]-path[t])_j
// ---------------------------------------------------------------------------
__global__ __launch_bounds__(256, 2) void sig_part_kernel(void)
{
    __shared__ float ps[65 * 64];      // [tt][ci]
    const int h = blockIdx.x, b = blockIdx.y, tid = threadIdx.x;
    const int tx = tid & 15, ty = tid >> 4;
    const float* pb = g_path + b * LSEQ * 64;

    float p0[4];
    #pragma unroll
    for (int i = 0; i < 4; i++) p0[i] = pb[ty * 4 + i];

    float acc[4][4] = {};

    const int tbeg = h * 256;
    const int tend = min((h + 1) * 256, LSEQ - 1);
    for (int t0 = tbeg; t0 < tend; t0 += 64) {
        const int steps = min(64, tend - t0);
        const int nrows = steps + 1;
        __syncthreads();
        for (int e = tid * 4; e < nrows * 64; e += 256 * 4) {
            float4 g = *(const float4*)&pb[t0 * 64 + e];
            *(float4*)&ps[e] = g;
        }
        __syncthreads();

        float4 cur = *(const float4*)&ps[tx * 4];
        #pragma unroll 4
        for (int t = 0; t < steps; t++) {
            float4 pf4 = *(const float4*)&ps[t * 64 + ty * 4];
            float4 nxt = *(const float4*)&ps[(t + 1) * 64 + tx * 4];
            float pf[4] = {pf4.x - p0[0], pf4.y - p0[1], pf4.z - p0[2], pf4.w - p0[3]};
            float df[4] = {nxt.x - cur.x, nxt.y - cur.y, nxt.z - cur.z, nxt.w - cur.w};
            #pragma unroll
            for (int i = 0; i < 4; i++)
                #pragma unroll
                for (int j = 0; j < 4; j++)
                    acc[i][j] += pf[i] * df[j];
            cur = nxt;
        }
    }

    float* sp = g_spart + (b * 2 + h) * 64 * 64;
    #pragma unroll
    for (int i = 0; i < 4; i++)
        #pragma unroll
        for (int j = 0; j < 4; j++)
            sp[(ty * 4 + i) * 64 + tx * 4 + j] = acc[i][j];
}

// ---------------------------------------------------------------------------
// Kernel 2b: combine partial S, Levy area + lvl1 + tail features.
// grid 128 (batch), 256 threads.
// ---------------------------------------------------------------------------
__global__ __launch_bounds__(256) void sig_combine_kernel(const float* __restrict__ x)
{
    __shared__ float red[256];
    const int b = blockIdx.x, tid = threadIdx.x;
    const float* pb = g_path + b * LSEQ * 64;
    const float* sp0 = g_spart + (b * 2 + 0) * 64 * 64;
    const float* sp1 = g_spart + (b * 2 + 1) * 64 * 64;
    float* fb = g_feat + b * IN_DIM;

    // tail: max-pool channel 64, static = channels 65.. at t=0
    {
        const float* xr = x + (b * XCH + C_IN) * LSEQ;
        float m = -3.402823466e+38f;
        #pragma unroll
        for (int t = tid; t < LSEQ; t += 256) m = fmaxf(m, xr[t]);
        red[tid] = m;
        __syncthreads();
        for (int s = 128; s > 0; s >>= 1) {
            if (tid < s) red[tid] = fmaxf(red[tid], red[tid + s]);
            __syncthreads();
        }
        if (tid == 0) fb[LOGSIG] = red[0];
        for (int c = tid; c < POSTC - 1; c += 256)
            fb[LOGSIG + 1 + c] = x[(b * XCH + C_IN + 1 + c) * LSEQ + 0];
    }

    if (tid < 64) fb[tid] = pb[(LSEQ - 1) * 64 + tid] - pb[tid];  // level 1

    for (int u = tid; u < 2016; u += 256) {
        int i = 0, rem = u;
        while (rem >= 63 - i) { rem -= 63 - i; i++; }
        int j = i + 1 + rem;
        float sij = sp0[i * 64 + j] + sp1[i * 64 + j];
        float sji = sp0[j * 64 + i] + sp1[j * 64 + i];
        fb[64 + u] = 0.5f * (sij - sji);
    }
}

// ---------------------------------------------------------------------------
// Split-K FC GEMM, double-buffered smem + register prefetch.
// part[z][m][n] = sum_{k in chunk z} A[m][k] * W[n][k]
// A: [M][K] row-major, W: [N][K] row-major. BK = 32, K % 32 == 0.
// 256 threads as 16(tx: n) x 16(ty: m); thread tile TM x TN.
// ---------------------------------------------------------------------------
template<int BM, int BN, int TM, int TN, int S>
__global__ __launch_bounds__(256, 2) void fc_part_kernel(
    const float* __restrict__ A, const float* __restrict__ W,
    float* __restrict__ part, int M, int N, int K)
{
    constexpr int BK = 32;
    constexpr int NA = (BM * BK) / 1024;   // float4 loads per thread (A)
    constexpr int NB = (BN * BK) / 1024;   // float4 loads per thread (B)
    __shared__ float aT[2][BK][BM + 4];
    __shared__ float bT[2][BK][BN + 4];

    const int m0 = blockIdx.y * BM, n0 = blockIdx.x * BN;
    const int z = blockIdx.z;
    const int chunks = K / BK;
    const int kb = (z * chunks / S) * BK;
    const int ke = ((z + 1) * chunks / S) * BK;
    const int tid = threadIdx.x, tx = tid & 15, ty = tid >> 4;

    float4 ra[NA], rb[NB];
    float acc[TM][TN] = {};

    auto fetch = [&](int k0) {
        #pragma unroll
        for (int i = 0; i < NA; i++) {
            int e = tid * 4 + i * 1024;
            ra[i] = *(const float4*)&A[(m0 + (e >> 5)) * K + k0 + (e & 31)];
        }
        #pragma unroll
        for (int i = 0; i < NB; i++) {
            int e = tid * 4 + i * 1024;
            rb[i] = *(const float4*)&W[(n0 + (e >> 5)) * K + k0 + (e & 31)];
        }
    };
    auto stage = [&](int buf) {
        #pragma unroll
        for (int i = 0; i < NA; i++) {
            int e = tid * 4 + i * 1024, r = e >> 5, c = e & 31;
            aT[buf][c + 0][r] = ra[i].x; aT[buf][c + 1][r] = ra[i].y;
            aT[buf][c + 2][r] = ra[i].z; aT[buf][c + 3][r] = ra[i].w;
        }
        #pragma unroll
        for (int i = 0; i < NB; i++) {
            int e = tid * 4 + i * 1024, r = e >> 5, c = e & 31;
            bT[buf][c + 0][r] = rb[i].x; bT[buf][c + 1][r] = rb[i].y;
            bT[buf][c + 2][r] = rb[i].z; bT[buf][c + 3][r] = rb[i].w;
        }
    };
    auto compute = [&](int buf) {
        #pragma unroll
        for (int kk = 0; kk < BK; kk++) {
            float af[TM], bf[TN];
            if (TM == 4) {
                float4 a4 = *(const float4*)&aT[buf][kk][ty * 4];
                af[0] = a4.x; af[1] = a4.y; af[2] = a4.z; af[3] = a4.w;
            } else {
                #pragma unroll
                for (int i = 0; i < TM; i++) af[i] = aT[buf][kk][ty * TM + i];
            }
            if (TN == 4) {
                float4 b4 = *(const float4*)&bT[buf][kk][tx * 4];
                bf[0] = b4.x; bf[1] = b4.y; bf[2] = b4.z; bf[3] = b4.w;
            } else {
                #pragma unroll
                for (int j = 0; j < TN; j++) bf[j] = bT[buf][kk][tx * TN + j];
            }
            #pragma unroll
            for (int i = 0; i < TM; i++)
                #pragma unroll
                for (int j = 0; j < TN; j++)
                    acc[i][j] += af[i] * bf[j];
        }
    };

    fetch(kb);
    stage(0);
    __syncthreads();
    int buf = 0;
    for (int k0 = kb + BK; k0 < ke; k0 += BK) {
        fetch(k0);          // overlaps with compute below
        compute(buf);
        stage(buf ^ 1);     // other buffer: no reader this iteration
        __syncthreads();    // staging visible before next compute
        buf ^= 1;
    }
    compute(buf);

    float* pz = part + (size_t)z * M * N;
    #pragma unroll
    for (int i = 0; i < TM; i++) {
        int m = m0 + ty * TM + i;
        #pragma unroll
        for (int j = 0; j < TN; j++) {
            int n = n0 + tx * TN + j;
            pz[m * N + n] = acc[i][j];
        }
    }
}

// reduce partials + bias (+ relu), float4-vectorized (M*N % 4 == 0, N % 4 == 0)
template<int S, bool RELU>
__global__ __launch_bounds__(256) void fc_reduce_kernel(
    const float* __restrict__ part, const float* __restrict__ bias,
    float* __restrict__ out, int M, int N)
{
    int idx = (blockIdx.x * 256 + threadIdx.x) * 4;
    if (idx >= M * N) return;
    int n = idx % N;
    float4 v = *(const float4*)&bias[n];
    #pragma unroll
    for (int z = 0; z < S; z++) {
        float4 p = *(const float4*)&part[(size_t)z * M * N + idx];
        v.x += p.x; v.y += p.y; v.z += p.z; v.w += p.w;
    }
    if (RELU) {
        v.x = fmaxf(v.x, 0.f); v.y = fmaxf(v.y, 0.f);
        v.z = fmaxf(v.z, 0.f); v.w = fmaxf(v.w, 0.f);
    }
    *(float4*)&out[idx] = v;
}

// ---------------------------------------------------------------------------
extern "C" void kernel_launch(void* const* d_in, const int* in_sizes, int n_in,
                              void* d_out, int out_size)
{
    const float* x      = (const float*)d_in[0];
    const float* conv_w = (const float*)d_in[1];
    const float* conv_b = (const float*)d_in[2];
    const float* fc1_w  = (const float*)d_in[3];
    const float* fc1_b  = (const float*)d_in[4];
    const float* fc2_w  = (const float*)d_in[5];
    const float* fc2_b  = (const float*)d_in[6];
    const float* fc3_w  = (const float*)d_in[7];
    const float* fc3_b  = (const float*)d_in[8];
    float* out = (float*)d_out;

    float *p_feat, *p_h1, *p_h2, *p_part;
    cudaGetSymbolAddress((void**)&p_feat, g_feat);
    cudaGetSymbolAddress((void**)&p_h1, g_h1);
    cudaGetSymbolAddress((void**)&p_h2, g_h2);
    cudaGetSymbolAddress((void**)&p_part, g_part);

    conv_tanh_kernel<<<dim3(LSEQ / 64, BATCH), 256>>>(x, conv_w, conv_b);
    sig_part_kernel<<<dim3(2, BATCH), 256>>>();
    sig_combine_kernel<<<BATCH, 256>>>(x);

    // fc1: 128 x 1024 x 2464, tiles 64x64, split-K 8 -> 256 blocks
    fc_part_kernel<64, 64, 4, 4, 8><<<dim3(HID / 64, BATCH / 64, 8), 256>>>(
        p_feat, fc1_w, p_part, BATCH, HID, IN_DIM);
    fc_reduce_kernel<8, true><<<(BATCH * HID / 4 + 255) / 256, 256>>>(
        p_part, fc1_b, p_h1, BATCH, HID);

    // fc2: 128 x 1024 x 1024, tiles 64x64, split-K 8 -> 256 blocks
    fc_part_kernel<64, 64, 4, 4, 8><<<dim3(HID / 64, BATCH / 64, 8), 256>>>(
        p_h1, fc2_w, p_part, BATCH, HID, HID);
    fc_reduce_kernel<8, true><<<(BATCH * HID / 4 + 255) / 256, 256>>>(
        p_part, fc2_b, p_h2, BATCH, HID);

    // fc3: 128 x 128 x 1024, tiles 32x32, split-K 16 -> 256 blocks (no relu)
    fc_part_kernel<32, 32, 2, 2, 16><<<dim3(OUT_DIM / 32, BATCH / 32, 16), 256>>>(
        p_h2, fc3_w, p_part, BATCH, OUT_DIM, HID);
    fc_reduce_kernel<16, false><<<(BATCH * OUT_DIM / 4 + 255) / 256, 256>>>(
        p_part, fc3_b, out, BATCH, OUT_DIM);
}